// round 6
// baseline (speedup 1.0000x reference)
#include <cuda_runtime.h>

// DynamicNet_17695265259799 — exact closed form of the reference.
//
// reference(): Wm = tril(W,-1) keeps W[i,j] only for i > j, but the scan
// fills nodes j = 1..n-1 in ASCENDING order, so at step j every potential
// source activation A[:,i], i > j is still exactly 0.0f. Hence
// s_j == b[j] exactly (0 * finite == 0 in IEEE fp32), the output node is
// linear, and the result is b[n-1] broadcast over the batch — independent
// of x and W for all finite inputs.
//
// R6 (converged): kernel is floor-bound by launch ramp (~5000 cyc) + L2
// store drain (~670 cyc for 4 MiB); measured dur band 6.66-6.91us is noise.
// Shape: 1024x256, one STG.128/thread (measured best). Exact-cover launch
// removes the bounds predicate from the hot SASS path:
//   LDG.E -> IMAD(addr) -> STG.E.128 -> EXIT.

__global__ __launch_bounds__(256)
void dynamicnet_broadcast_exact(const float* __restrict__ bias_last,
                                float4* __restrict__ out4) {
    const float v = __ldg(bias_last);
    const int tid = blockIdx.x * blockDim.x + threadIdx.x;
    out4[tid] = make_float4(v, v, v, v);   // guard-free: grid exactly covers n4
}

// Guarded fallback for sizes not divisible by 1024 float4s (never taken for
// out_size = 1048576).
__global__ __launch_bounds__(256)
void dynamicnet_broadcast_guarded(const float* __restrict__ bias_last,
                                  float4* __restrict__ out4, int n4) {
    const float v = __ldg(bias_last);
    const int tid = blockIdx.x * blockDim.x + threadIdx.x;
    if (tid < n4) out4[tid] = make_float4(v, v, v, v);
}

__global__ void dynamicnet_tail_kernel(const float* __restrict__ bias_last,
                                       float* __restrict__ out,
                                       int start, int out_elems) {
    const float v = __ldg(bias_last);
    const int i = start + threadIdx.x;
    if (i < out_elems) out[i] = v;
}

extern "C" void kernel_launch(void* const* d_in, const int* in_sizes, int n_in,
                              void* d_out, int out_size) {
    // metadata order: x [BATCH,1] f32, W [n,n] f32, b [n] f32
    const float* bias = (const float*)d_in[2];
    const float* bias_last = bias + (in_sizes[2] - 1);  // &b[65]

    float* out = (float*)d_out;
    float4* out4 = reinterpret_cast<float4*>(out);
    const int n4 = out_size >> 2;  // 262144 float4 slots

    const int threads = 256;
    if (n4 > 0 && (n4 % threads) == 0) {
        // Exact cover: 1024 blocks for out_size = 1048576. No predicate.
        dynamicnet_broadcast_exact<<<n4 / threads, threads>>>(bias_last, out4);
    } else if (n4 > 0) {
        dynamicnet_broadcast_guarded<<<(n4 + threads - 1) / threads, threads>>>(
            bias_last, out4, n4);
    }

    const int tail = out_size - (n4 << 2);
    if (tail > 0) {
        dynamicnet_tail_kernel<<<1, 32>>>(bias_last, out, n4 << 2, out_size);
    }
}

// round 7
// speedup vs baseline: 1.0385x; 1.0385x over previous
#include <cuda_runtime.h>

// DynamicNet_17695265259799 — exact closed form of the reference.
//
// reference(): Wm = tril(W,-1) keeps W[i,j] only for i > j, but the scan
// fills nodes j = 1..n-1 in ASCENDING order, so at step j every potential
// source activation A[:,i], i > j is still exactly 0.0f. Hence
// s_j == b[j] exactly (0 * finite == 0 in IEEE fp32), the output node is
// linear, and the result is b[n-1] broadcast over the batch — independent
// of x and W for all finite inputs.
//
// R7: last shape axis — fewer/fatter CTAs. 512 blocks x 512 threads,
// one STG.128/thread (same 262144 threads, 8192 warps). Halves CTA-dispatch
// count vs the 1024x256 baseline; everything else identical.
// Measured history: 1024x256=4.22-4.67us, 256x256x4=4.61, 2048x128=6.08.

__global__ __launch_bounds__(512)
void dynamicnet_broadcast_exact(const float* __restrict__ bias_last,
                                float4* __restrict__ out4) {
    const float v = __ldg(bias_last);
    const int tid = blockIdx.x * blockDim.x + threadIdx.x;
    out4[tid] = make_float4(v, v, v, v);   // guard-free: grid exactly covers n4
}

// Guarded fallback for sizes not exactly covered (never taken here).
__global__ __launch_bounds__(256)
void dynamicnet_broadcast_guarded(const float* __restrict__ bias_last,
                                  float4* __restrict__ out4, int n4) {
    const float v = __ldg(bias_last);
    const int tid = blockIdx.x * blockDim.x + threadIdx.x;
    if (tid < n4) out4[tid] = make_float4(v, v, v, v);
}

__global__ void dynamicnet_tail_kernel(const float* __restrict__ bias_last,
                                       float* __restrict__ out,
                                       int start, int out_elems) {
    const float v = __ldg(bias_last);
    const int i = start + threadIdx.x;
    if (i < out_elems) out[i] = v;
}

extern "C" void kernel_launch(void* const* d_in, const int* in_sizes, int n_in,
                              void* d_out, int out_size) {
    // metadata order: x [BATCH,1] f32, W [n,n] f32, b [n] f32
    const float* bias = (const float*)d_in[2];
    const float* bias_last = bias + (in_sizes[2] - 1);  // &b[65]

    float* out = (float*)d_out;
    float4* out4 = reinterpret_cast<float4*>(out);
    const int n4 = out_size >> 2;  // 262144 float4 slots

    const int threads = 512;
    if (n4 > 0 && (n4 % threads) == 0) {
        // Exact cover: 512 blocks x 512 threads for out_size = 1048576.
        dynamicnet_broadcast_exact<<<n4 / threads, threads>>>(bias_last, out4);
    } else if (n4 > 0) {
        dynamicnet_broadcast_guarded<<<(n4 + 255) / 256, 256>>>(
            bias_last, out4, n4);
    }

    const int tail = out_size - (n4 << 2);
    if (tail > 0) {
        dynamicnet_tail_kernel<<<1, 32>>>(bias_last, out, n4 << 2, out_size);
    }
}